// round 9
// baseline (speedup 1.0000x reference)
#include <cuda_runtime.h>
#include <cuda_bf16.h>
#include <math.h>
#include <stdint.h>

#define NUM_CLASSES 13
#define C1 14                        // NUM_CLASSES+1
#define ROWS 1600000                 // 32*1000*50
#define TPB 256
#define TPT 2                        // logit tiles per block
#define GRID (ROWS / (TPB * TPT))    // 3125
#define LOG4 (TPB * C1 / 4)          // 896 float4 per logit tile
#define DOA4_BLK (TPB * TPT * 3 / 4) // 384 float4 per block per doa array
#define W_CLASS 1.0
#define W_DOA   2.0

__device__ double g_acc[3];
__device__ unsigned int g_ticket;

__device__ __forceinline__ unsigned int smem_u32(const void* p) {
    return (unsigned int)__cvta_generic_to_shared(p);
}
__device__ __forceinline__ void cpa16(unsigned int d, const void* s) {
    asm volatile("cp.async.cg.shared.global [%0], [%1], 16;" :: "r"(d), "l"(s));
}
__device__ __forceinline__ void cp_commit() {
    asm volatile("cp.async.commit_group;");
}
template<int N> __device__ __forceinline__ void cp_wait() {
    asm volatile("cp.async.wait_group %0;" :: "n"(N));
}

__global__ __launch_bounds__(TPB, 6)
void loss_fused_kernel(const float* __restrict__ pred_logits,
                       const float* __restrict__ pred_doa,
                       const float* __restrict__ target_doa,
                       const float* __restrict__ empty_weight,
                       const int*   __restrict__ target_classes,
                       float* __restrict__ out) {
    __shared__ __align__(16) float s_log[TPT][TPB * C1];   // 2 x 14336 B, no reuse
    __shared__ float s_ew[C1];
    __shared__ float r_ce[8], r_ab[8], r_ct[8];
    __shared__ bool  s_last;

    const int tid = threadIdx.x;
    const int base = blockIdx.x * TPT;

    if (tid < C1) s_ew[tid] = empty_weight[tid];

    auto issue = [&](int buf, int tile) {
        const size_t r0 = (size_t)tile * TPB;
        const float4* gl = reinterpret_cast<const float4*>(pred_logits + r0 * C1);
        unsigned int dl = smem_u32(&s_log[buf][0]);
        cpa16(dl + (unsigned int)(tid)       * 16u, gl + tid);
        cpa16(dl + (unsigned int)(tid + 256) * 16u, gl + tid + 256);
        cpa16(dl + (unsigned int)(tid + 512) * 16u, gl + tid + 512);
        if (tid < LOG4 - 768)                                   // 128 threads
            cpa16(dl + (unsigned int)(tid + 768) * 16u, gl + tid + 768);
        cp_commit();
    };

    // ---- prologue: both tiles in flight immediately ----
    issue(0, base);
    issue(1, base + 1);

    // ---- per-thread targets, coalesced ----
    int tg0 = __ldg(target_classes + (size_t)base * TPB + tid);
    int tg1 = __ldg(target_classes + (size_t)(base + 1) * TPB + tid);

    // ---- DOA phase: coalesced float4 LDG stream, overlapped with cp.async flight ----
    float acc_ab = 0.0f;
    {
        const float4* pd4 = reinterpret_cast<const float4*>(pred_doa);
        const float4* td4 = reinterpret_cast<const float4*>(target_doa);
        const int f4base = blockIdx.x * DOA4_BLK;
        #pragma unroll
        for (int u = 0; u < 2; u++) {
            int i = u * TPB + tid;
            if (u == 0 || i < DOA4_BLK) {           // u=1: only tid<128
                int g = f4base + i;
                float4 p = __ldg(pd4 + g);
                float4 t = __ldg(td4 + g);
                int e = g * 4;
                int q0 = e / 3;
                int r  = e - q0 * 3;                // e % 3
                float m0 = (__ldg(target_classes + q0)     != NUM_CLASSES) ? 1.0f : 0.0f;
                float m1 = (__ldg(target_classes + q0 + 1) != NUM_CLASSES) ? 1.0f : 0.0f;
                float mA = (r + 0 >= 3) ? m1 : m0;
                float mB = (r + 1 >= 3) ? m1 : m0;
                float mC = (r + 2 >= 3) ? m1 : m0;
                acc_ab += mA * fabsf(p.x - t.x) + mB * fabsf(p.y - t.y)
                        + mC * fabsf(p.z - t.z) + m1 * fabsf(p.w - t.w);
            }
        }
    }

    // ---- CE phase: 2 tiles, no buffer reuse => single barrier per tile ----
    float acc_ce = 0.0f, acc_ct = 0.0f;

    #pragma unroll
    for (int k = 0; k < TPT; k++) {
        const int tg = (k == 0) ? tg0 : tg1;

        if (k == 0) cp_wait<1>(); else cp_wait<0>();
        __syncthreads();                 // make other threads' copies of tile k visible

        const float2* rp = reinterpret_cast<const float2*>(&s_log[k][tid * C1]);
        float v[C1];
        #pragma unroll
        for (int j = 0; j < C1 / 2; j++) {
            float2 p = rp[j];
            v[2 * j] = p.x; v[2 * j + 1] = p.y;
        }
        float m = fmaxf(fmaxf(fmaxf(fmaxf(v[0], v[1]), fmaxf(v[2], v[3])),
                              fmaxf(fmaxf(v[4], v[5]), fmaxf(v[6], v[7]))),
                        fmaxf(fmaxf(fmaxf(v[8], v[9]), fmaxf(v[10], v[11])),
                              fmaxf(v[12], v[13])));
        float s = 0.0f;
        #pragma unroll
        for (int j = 0; j < C1; j++) s += __expf(v[j] - m);
        float vt = s_log[k][tid * C1 + tg];       // single dynamic LDS
        acc_ce += s_ew[tg] * (__logf(s) + m - vt);
        if (tg != NUM_CLASSES) acc_ct += 1.0f;
    }

    // ---- block reduction ----
    #pragma unroll
    for (int off = 16; off > 0; off >>= 1) {
        acc_ce += __shfl_down_sync(0xFFFFFFFFu, acc_ce, off);
        acc_ab += __shfl_down_sync(0xFFFFFFFFu, acc_ab, off);
        acc_ct += __shfl_down_sync(0xFFFFFFFFu, acc_ct, off);
    }
    const int lane = tid & 31, wid = tid >> 5;
    if (lane == 0) { r_ce[wid] = acc_ce; r_ab[wid] = acc_ab; r_ct[wid] = acc_ct; }
    __syncthreads();

    if (tid == 0) {
        float tce = 0.0f, tab = 0.0f, tct = 0.0f;
        #pragma unroll
        for (int w = 0; w < 8; w++) { tce += r_ce[w]; tab += r_ab[w]; tct += r_ct[w]; }
        atomicAdd(&g_acc[0], (double)tce);
        atomicAdd(&g_acc[1], (double)tab);
        atomicAdd(&g_acc[2], (double)tct);
        __threadfence();
        unsigned int ticket = atomicAdd(&g_ticket, 1u);
        s_last = (ticket == GRID - 1);
    }
    __syncthreads();

    if (s_last && tid == 0) {
        double ce = g_acc[0], ab = g_acc[1], ct = g_acc[2];
        double loss_class = ce / (double)ROWS;
        double n_elems = ct * 3.0;
        double loss_doa = (n_elems > 0.0) ? (ab / fmax(n_elems, 1.0)) : 0.0;
        out[0] = (float)(W_CLASS * loss_class + W_DOA * loss_doa);
        g_acc[0] = 0.0; g_acc[1] = 0.0; g_acc[2] = 0.0;
        __threadfence();
        g_ticket = 0u;
    }
}

extern "C" void kernel_launch(void* const* d_in, const int* in_sizes, int n_in,
                              void* d_out, int out_size) {
    const float* pred_logits    = (const float*)d_in[0];
    const float* pred_doa       = (const float*)d_in[1];
    const float* target_doa     = (const float*)d_in[2];
    const float* empty_weight   = (const float*)d_in[3];
    const int*   target_classes = (const int*)d_in[4];
    float* out = (float*)d_out;

    loss_fused_kernel<<<GRID, TPB>>>(pred_logits, pred_doa, target_doa,
                                     empty_weight, target_classes, out);
}

// round 10
// speedup vs baseline: 1.0696x; 1.0696x over previous
#include <cuda_runtime.h>
#include <cuda_bf16.h>
#include <math.h>
#include <stdint.h>

#define NUM_CLASSES 13
#define C1 14                         // NUM_CLASSES+1
#define ROWS 1600000                  // 32*1000*50
#define TPB 256
#define WARPS 8
#define WROWS 32                      // rows per warp-tile
#define TPT 5                         // warp-tiles per warp
#define BLK_ROWS (TPB * TPT)          // 1280 rows per block
#define GRID (ROWS / BLK_ROWS)        // 1250
#define WT4 (WROWS * C1 / 4)          // 112 float4 per warp-tile
#define DOA4_BLK (BLK_ROWS * 3 / 4)   // 960 float4 per block per doa array
#define W_CLASS 1.0
#define W_DOA   2.0

__device__ double g_acc[3];
__device__ unsigned int g_ticket;

__device__ __forceinline__ unsigned int smem_u32(const void* p) {
    return (unsigned int)__cvta_generic_to_shared(p);
}
__device__ __forceinline__ void cpa16(unsigned int d, const void* s) {
    asm volatile("cp.async.cg.shared.global [%0], [%1], 16;" :: "r"(d), "l"(s));
}
__device__ __forceinline__ void cp_commit() {
    asm volatile("cp.async.commit_group;");
}
template<int N> __device__ __forceinline__ void cp_wait() {
    asm volatile("cp.async.wait_group %0;" :: "n"(N));
}

__global__ __launch_bounds__(TPB, 6)
void loss_fused_kernel(const float* __restrict__ pred_logits,
                       const float* __restrict__ pred_doa,
                       const float* __restrict__ target_doa,
                       const float* __restrict__ empty_weight,
                       const int*   __restrict__ target_classes,
                       float* __restrict__ out) {
    // warp-private double buffers: [warp][buf][32 rows * 14 floats]
    __shared__ __align__(16) float s_log[WARPS][2][WROWS * C1];   // 8*2*1792B = 28672 B
    __shared__ float r_ce[8], r_ab[8], r_ct[8];
    __shared__ bool  s_last;

    const int tid  = threadIdx.x;
    const int lane = tid & 31;
    const int wid  = tid >> 5;

    // warp-contiguous row ownership
    const size_t wbase = (size_t)blockIdx.x * BLK_ROWS + (size_t)wid * (WROWS * TPT);

    // ---- warp-private cp.async issue: 112 float4, lanes 0..27 x4 ----
    auto issue = [&](int buf, int t) {
        const float4* gl = reinterpret_cast<const float4*>(pred_logits + (wbase + (size_t)t * WROWS) * C1);
        unsigned int dl = smem_u32(&s_log[wid][buf][0]);
        if (lane < 28) {
            #pragma unroll
            for (int k = 0; k < 4; k++)
                cpa16(dl + (unsigned int)(lane + 28 * k) * 16u, gl + lane + 28 * k);
        }
        cp_commit();      // all lanes commit (empty groups keep counts aligned)
    };

    // ---- prologue: 2 warp-tiles in flight, no block barrier anywhere ----
    issue(0, 0);
    issue(1, 1);

    // ---- per-thread targets for all 5 tiles (coalesced) ----
    int tgs[TPT];
    #pragma unroll
    for (int k = 0; k < TPT; k++)
        tgs[k] = __ldg(target_classes + wbase + (size_t)k * WROWS + lane);

    // ---- DOA phase: coalesced float4 LDG stream, overlaps cp.async flight ----
    float acc_ab = 0.0f;
    {
        const float4* pd4 = reinterpret_cast<const float4*>(pred_doa);
        const float4* td4 = reinterpret_cast<const float4*>(target_doa);
        const int f4base = blockIdx.x * DOA4_BLK;
        #pragma unroll
        for (int u = 0; u < 4; u++) {
            int i = u * TPB + tid;
            if (u < 3 || i < DOA4_BLK) {
                int g = f4base + i;
                float4 p = __ldg(pd4 + g);
                float4 t = __ldg(td4 + g);
                int e = g * 4;
                int q0 = e / 3;
                int r  = e - q0 * 3;
                float m0 = (__ldg(target_classes + q0)     != NUM_CLASSES) ? 1.0f : 0.0f;
                float m1 = (__ldg(target_classes + q0 + 1) != NUM_CLASSES) ? 1.0f : 0.0f;
                float mA = (r + 0 >= 3) ? m1 : m0;
                float mB = (r + 1 >= 3) ? m1 : m0;
                float mC = (r + 2 >= 3) ? m1 : m0;
                acc_ab += mA * fabsf(p.x - t.x) + mB * fabsf(p.y - t.y)
                        + mC * fabsf(p.z - t.z) + m1 * fabsf(p.w - t.w);
            }
        }
    }

    // ---- CE phase: warp-private pipeline, __syncwarp only ----
    float acc_ce = 0.0f, acc_ct = 0.0f;

    #pragma unroll
    for (int k = 0; k < TPT; k++) {
        const int buf = k & 1;
        const int tg = tgs[k];

        if (k == TPT - 1) cp_wait<0>(); else cp_wait<1>();
        __syncwarp();                    // other lanes' copies of tile k visible

        const float* rowp = &s_log[wid][buf][lane * C1];
        const float2* rp = reinterpret_cast<const float2*>(rowp);
        float v[C1];
        #pragma unroll
        for (int j = 0; j < C1 / 2; j++) {
            float2 p = rp[j];
            v[2 * j] = p.x; v[2 * j + 1] = p.y;
        }
        float m = fmaxf(fmaxf(fmaxf(fmaxf(v[0], v[1]), fmaxf(v[2], v[3])),
                              fmaxf(fmaxf(v[4], v[5]), fmaxf(v[6], v[7]))),
                        fmaxf(fmaxf(fmaxf(v[8], v[9]), fmaxf(v[10], v[11])),
                              fmaxf(v[12], v[13])));
        float s = 0.0f;
        #pragma unroll
        for (int j = 0; j < C1; j++) s += __expf(v[j] - m);
        float vt = rowp[tg];                          // single dynamic LDS
        float w  = __ldg(empty_weight + tg);          // 56B table, L1-resident
        acc_ce += w * (__logf(s) + m - vt);
        if (tg != NUM_CLASSES) acc_ct += 1.0f;

        __syncwarp();                    // all lanes done reading buf
        if (k + 2 < TPT) issue(buf, k + 2);
    }

    // ---- block reduction (single __syncthreads in the whole kernel body) ----
    #pragma unroll
    for (int off = 16; off > 0; off >>= 1) {
        acc_ce += __shfl_down_sync(0xFFFFFFFFu, acc_ce, off);
        acc_ab += __shfl_down_sync(0xFFFFFFFFu, acc_ab, off);
        acc_ct += __shfl_down_sync(0xFFFFFFFFu, acc_ct, off);
    }
    if (lane == 0) { r_ce[wid] = acc_ce; r_ab[wid] = acc_ab; r_ct[wid] = acc_ct; }
    __syncthreads();

    if (tid == 0) {
        float tce = 0.0f, tab = 0.0f, tct = 0.0f;
        #pragma unroll
        for (int w = 0; w < 8; w++) { tce += r_ce[w]; tab += r_ab[w]; tct += r_ct[w]; }
        atomicAdd(&g_acc[0], (double)tce);
        atomicAdd(&g_acc[1], (double)tab);
        atomicAdd(&g_acc[2], (double)tct);
        __threadfence();
        unsigned int ticket = atomicAdd(&g_ticket, 1u);
        s_last = (ticket == GRID - 1);
    }
    __syncthreads();

    if (s_last && tid == 0) {
        double ce = g_acc[0], ab = g_acc[1], ct = g_acc[2];
        double loss_class = ce / (double)ROWS;
        double n_elems = ct * 3.0;
        double loss_doa = (n_elems > 0.0) ? (ab / fmax(n_elems, 1.0)) : 0.0;
        out[0] = (float)(W_CLASS * loss_class + W_DOA * loss_doa);
        g_acc[0] = 0.0; g_acc[1] = 0.0; g_acc[2] = 0.0;
        __threadfence();
        g_ticket = 0u;
    }
}

extern "C" void kernel_launch(void* const* d_in, const int* in_sizes, int n_in,
                              void* d_out, int out_size) {
    const float* pred_logits    = (const float*)d_in[0];
    const float* pred_doa       = (const float*)d_in[1];
    const float* target_doa     = (const float*)d_in[2];
    const float* empty_weight   = (const float*)d_in[3];
    const int*   target_classes = (const int*)d_in[4];
    float* out = (float*)d_out;

    loss_fused_kernel<<<GRID, TPB>>>(pred_logits, pred_doa, target_doa,
                                     empty_weight, target_classes, out);
}